// round 3
// baseline (speedup 1.0000x reference)
#include <cuda_runtime.h>
#include <math.h>

#define BB 16
#define TT 512
#define NCH 32
#define DD 512
#define KQ 96          // 3*32 contraction length

#define BM 128
#define BN 64
#define XS_STRIDE 33
#define BS_STRIDE 65

__device__ float g_T[TT * DD];   // sinusoid table: row r, col d
__device__ int   g_cnt[BB];      // per-batch count of channels with argmax == Nyquist

// ---------------------------------------------------------------------------
// Kernel 1: build fixed sinusoid table in double precision (matches numpy f64
// table rounded to f32), and zero the per-batch counters.
// ---------------------------------------------------------------------------
__global__ void build_table_kernel() {
    int t = blockIdx.x;
    if (blockIdx.x == 0 && threadIdx.x < BB) g_cnt[threadIdx.x] = 0;
    const double k = 9.210340371976184 / 512.0;   // log(10000)/d_model
    for (int d = threadIdx.x; d < DD; d += blockDim.x) {
        int j2 = d & ~1;
        double div = exp(-(double)j2 * k);
        double ang = (double)t * div;
        g_T[t * DD + d] = (d & 1) ? (float)cos(ang) : (float)sin(ang);
    }
}

// ---------------------------------------------------------------------------
// Kernel 2: per-(b,n) brute-force DFT over 257 rfft bins, block argmax with
// first-index tie-break (matches top_k), atomically count Nyquist winners.
// ---------------------------------------------------------------------------
__global__ void dft_argmax_kernel(const float* __restrict__ x) {
    __shared__ float seq[TT];
    __shared__ float ctab[TT];
    __shared__ float smax[256];
    __shared__ int   sidx[256];

    int bn = blockIdx.x;          // 0..511
    int b = bn >> 5;
    int n = bn & 31;
    int tid = threadIdx.x;

    const float w0 = 6.283185307179586f / 512.0f;
    for (int i = tid; i < TT; i += blockDim.x) {
        seq[i]  = x[(b * TT + i) * NCH + n];
        ctab[i] = cosf((float)i * w0);
    }
    __syncthreads();

    float best = -1.0f;
    int   bidx = 0;
    for (int kk = tid; kk <= TT / 2; kk += blockDim.x) {
        float re = 0.f, im = 0.f;
        for (int t = 0; t < TT; t++) {
            int ci = (kk * t) & (TT - 1);
            float c = ctab[ci];
            float s = ctab[(ci - 128) & (TT - 1)];  // sin(th) = cos(th - pi/2)
            float v = seq[t];
            re += v * c;
            im += v * s;
        }
        float m = re * re + im * im;
        if (m > best) { best = m; bidx = kk; }   // strict > keeps smaller k on tie
    }
    smax[tid] = best;
    sidx[tid] = bidx;
    __syncthreads();
    for (int s = 128; s > 0; s >>= 1) {
        if (tid < s) {
            bool take = (smax[tid + s] > smax[tid]) ||
                        (smax[tid + s] == smax[tid] && sidx[tid + s] < sidx[tid]);
            if (take) { smax[tid] = smax[tid + s]; sidx[tid] = sidx[tid + s]; }
        }
        __syncthreads();
    }
    if (tid == 0 && sidx[0] == TT / 2) atomicAdd(&g_cnt[b], 1);
}

// ---------------------------------------------------------------------------
// Kernel 3: fused circular conv (GEMM, K=96) + temporal rows + cycle rows.
// Tile: 128(t) x 64(d), 256 threads, 8x4 microtile.
// ---------------------------------------------------------------------------
__global__ __launch_bounds__(256) void fused_main_kernel(
    const float* __restrict__ x,
    const int*   __restrict__ xm,
    const float* __restrict__ w,
    float*       __restrict__ out)
{
    __shared__ float Xs[(BM + 2) * XS_STRIDE];  // rows t0-1 .. t0+BM
    __shared__ float Bs[KQ * BS_STRIDE];        // Bs[q][dd] = w[(d0+dd)*96 + q]
    __shared__ int4  Ms[BM];                    // x_mark rows

    int b  = blockIdx.z;
    int t0 = blockIdx.y * BM;
    int d0 = blockIdx.x * BN;
    int tid = threadIdx.x;

    for (int i = tid; i < (BM + 2) * NCH; i += 256) {
        int r = i >> 5;
        int c = i & 31;
        int tt = (t0 + r - 1) & (TT - 1);       // circular pad
        Xs[r * XS_STRIDE + c] = x[(b * TT + tt) * NCH + c];
    }
    for (int i = tid; i < KQ * BN; i += 256) {
        int dd = i / KQ;
        int q  = i - dd * KQ;
        Bs[q * BS_STRIDE + dd] = w[(d0 + dd) * KQ + q];
    }
    for (int i = tid; i < BM; i += 256) {
        Ms[i] = ((const int4*)xm)[b * TT + t0 + i];
    }
    __syncthreads();

    int tx = tid & 15;       // d
    int ty = tid >> 4;       // t
    int tbase = ty * 8;

    float acc[8][4];
#pragma unroll
    for (int i = 0; i < 8; i++)
#pragma unroll
        for (int j = 0; j < 4; j++) acc[i][j] = 0.f;

#pragma unroll
    for (int k = 0; k < 3; k++) {
#pragma unroll 4
        for (int c = 0; c < NCH; c++) {
            float a[8], bv[4];
            int q = c * 3 + k;
#pragma unroll
            for (int i = 0; i < 8; i++)
                a[i] = Xs[(tbase + i + k) * XS_STRIDE + c];
#pragma unroll
            for (int j = 0; j < 4; j++)
                bv[j] = Bs[q * BS_STRIDE + tx + 16 * j];
#pragma unroll
            for (int i = 0; i < 8; i++)
#pragma unroll
                for (int j = 0; j < 4; j++)
                    acc[i][j] += a[i] * bv[j];
        }
    }

    int cnt = g_cnt[b];
    float ca = (float)(32 - cnt) * 0.03125f;   // weight on T[t]
    float cc = (float)cnt * 0.03125f;          // weight on T[0] = (0,1,0,1,...)

#pragma unroll
    for (int i = 0; i < 8; i++) {
        int tl = tbase + i;
        int tg = t0 + tl;
        int4 m = Ms[tl];
        const float* Tt  = &g_T[tg  * DD + d0];
        const float* Tm0 = &g_T[m.x * DD + d0];
        const float* Tm1 = &g_T[m.y * DD + d0];
        const float* Tm2 = &g_T[m.z * DD + d0];
        const float* Tm3 = &g_T[m.w * DD + d0];
        float* orow = &out[((size_t)(b * TT + tg)) * DD + d0];
#pragma unroll
        for (int j = 0; j < 4; j++) {
            int dl = tx + 16 * j;
            int dg = d0 + dl;
            float v = acc[i][j]
                    + Tm0[dl] + Tm1[dl] + Tm2[dl] + Tm3[dl]
                    + ca * Tt[dl]
                    + ((dg & 1) ? cc : 0.f);
            orow[dl] = v;
        }
    }
}

// ---------------------------------------------------------------------------
extern "C" void kernel_launch(void* const* d_in, const int* in_sizes, int n_in,
                              void* d_out, int out_size) {
    const float* x  = (const float*)d_in[0];   // (16,512,32)
    const int*   xm = (const int*)  d_in[1];   // (16,512,4)
    const float* w  = (const float*)d_in[2];   // (512,32,3)
    float* out = (float*)d_out;                // (16,512,512)

    build_table_kernel<<<TT, 256>>>();
    dft_argmax_kernel<<<BB * NCH, 256>>>(x);
    dim3 grid(DD / BN, TT / BM, BB);
    fused_main_kernel<<<grid, 256>>>(x, xm, w, out);
}

// round 6
// speedup vs baseline: 2.0141x; 2.0141x over previous
#include <cuda_runtime.h>
#include <math.h>

#define BB 16
#define TT 512
#define NCH 32
#define DD 512
#define KQ 96          // 3*32 contraction length

#define BM 128
#define BN 64
#define XS_STRIDE 33
#define BS_STRIDE 65

__device__ float g_T[TT * DD];   // sinusoid table: row r, col d
__device__ int   g_cnt[BB];      // per-batch count of channels with argmax == Nyquist

// ---------------------------------------------------------------------------
// Kernel 1: build fixed sinusoid table in FP32 (expf + sincosf, few-ulp err;
// threshold is 1e-3 so this is ample), and zero the per-batch counters.
// One block per t-row, one float2 (sin,cos pair) per thread.
// ---------------------------------------------------------------------------
__global__ void build_table_kernel() {
    int t = blockIdx.x;
    if (blockIdx.x == 0 && threadIdx.x < BB) g_cnt[threadIdx.x] = 0;
    const float k = 0.01798894603f;            // log(10000)/512
    int d2 = threadIdx.x;                      // 0..255
    float div = expf(-(float)(2 * d2) * k);
    float ang = (float)t * div;
    float s, c;
    sincosf(ang, &s, &c);
    ((float2*)g_T)[t * (DD / 2) + d2] = make_float2(s, c);
}

// ---------------------------------------------------------------------------
// Kernel 2: per-(b,n) DFT argmax over 257 rfft bins via register phase
// rotation (no twiddle table, no bank conflicts). 4 independent rotators
// stepped by 4*theta break the serial FMA chain. Thread 0 handles the two
// trivial bins (0 = plain sum, 256 = alternating sum). Tie-break keeps the
// smaller bin index (matches lax.top_k).
// ---------------------------------------------------------------------------
__global__ void dft_argmax_kernel(const float* __restrict__ x) {
    __shared__ float seq[TT];
    __shared__ float smax[256];
    __shared__ int   sidx[256];

    int bn = blockIdx.x;          // 0..511
    int b = bn >> 5;
    int n = bn & 31;
    int tid = threadIdx.x;

    for (int i = tid; i < TT; i += blockDim.x)
        seq[i] = x[(b * TT + i) * NCH + n];
    __syncthreads();

    float best;
    int   bidx;

    if (tid == 0) {
        // bin 0: |sum x|^2 ; bin 256: |sum (-1)^t x|^2
        float s0 = 0.f, s1 = 0.f;
        for (int t = 0; t < TT; t += 2) {
            float a = seq[t], c = seq[t + 1];
            s0 += a + c;
            s1 += a - c;
        }
        best = s0 * s0;
        bidx = 0;
        float m256 = s1 * s1;
        if (m256 > best) { best = m256; bidx = 256; }
    } else {
        int kk = tid;             // bins 1..255
        float th = 6.283185307179586f * (float)kk * (1.0f / 512.0f);
        float c[4], s[4], re[4], im[4];
        float ct4, st4;
        sincosf(4.0f * th, &st4, &ct4);
        c[0] = 1.f; s[0] = 0.f;
#pragma unroll
        for (int j = 1; j < 4; j++) sincosf((float)j * th, &s[j], &c[j]);
#pragma unroll
        for (int j = 0; j < 4; j++) { re[j] = 0.f; im[j] = 0.f; }

        for (int t = 0; t < TT; t += 4) {
#pragma unroll
            for (int j = 0; j < 4; j++) {
                float v = seq[t + j];
                re[j] = fmaf(v, c[j], re[j]);
                im[j] = fmaf(v, s[j], im[j]);
            }
#pragma unroll
            for (int j = 0; j < 4; j++) {
                float cn = fmaf(c[j], ct4, -s[j] * st4);
                s[j] = fmaf(s[j], ct4, c[j] * st4);
                c[j] = cn;
            }
        }
        float R = (re[0] + re[1]) + (re[2] + re[3]);
        float I = (im[0] + im[1]) + (im[2] + im[3]);
        best = R * R + I * I;
        bidx = kk;
    }

    smax[tid] = best;
    sidx[tid] = bidx;
    __syncthreads();
    for (int sft = 128; sft > 0; sft >>= 1) {
        if (tid < sft) {
            bool take = (smax[tid + sft] > smax[tid]) ||
                        (smax[tid + sft] == smax[tid] && sidx[tid + sft] < sidx[tid]);
            if (take) { smax[tid] = smax[tid + sft]; sidx[tid] = sidx[tid + sft]; }
        }
        __syncthreads();
    }
    if (tid == 0 && sidx[0] == 256) atomicAdd(&g_cnt[b], 1);
}

// ---------------------------------------------------------------------------
// Kernel 3: fused circular conv (GEMM, K=96) + temporal rows + cycle rows.
// Tile: 128(t) x 64(d), 256 threads, 8x4 microtile.
// ---------------------------------------------------------------------------
__global__ __launch_bounds__(256) void fused_main_kernel(
    const float* __restrict__ x,
    const int*   __restrict__ xm,
    const float* __restrict__ w,
    float*       __restrict__ out)
{
    __shared__ float Xs[(BM + 2) * XS_STRIDE];  // rows t0-1 .. t0+BM
    __shared__ float Bs[KQ * BS_STRIDE];        // Bs[q][dd] = w[(d0+dd)*96 + q]
    __shared__ int4  Ms[BM];                    // x_mark rows

    int b  = blockIdx.z;
    int t0 = blockIdx.y * BM;
    int d0 = blockIdx.x * BN;
    int tid = threadIdx.x;

    for (int i = tid; i < (BM + 2) * NCH; i += 256) {
        int r = i >> 5;
        int c = i & 31;
        int tt = (t0 + r - 1) & (TT - 1);       // circular pad
        Xs[r * XS_STRIDE + c] = x[(b * TT + tt) * NCH + c];
    }
    for (int i = tid; i < KQ * BN; i += 256) {
        int dd = i / KQ;
        int q  = i - dd * KQ;
        Bs[q * BS_STRIDE + dd] = w[(d0 + dd) * KQ + q];
    }
    for (int i = tid; i < BM; i += 256) {
        Ms[i] = ((const int4*)xm)[b * TT + t0 + i];
    }
    __syncthreads();

    int tx = tid & 15;       // d
    int ty = tid >> 4;       // t
    int tbase = ty * 8;

    float acc[8][4];
#pragma unroll
    for (int i = 0; i < 8; i++)
#pragma unroll
        for (int j = 0; j < 4; j++) acc[i][j] = 0.f;

#pragma unroll
    for (int k = 0; k < 3; k++) {
#pragma unroll 4
        for (int c = 0; c < NCH; c++) {
            float a[8], bv[4];
            int q = c * 3 + k;
#pragma unroll
            for (int i = 0; i < 8; i++)
                a[i] = Xs[(tbase + i + k) * XS_STRIDE + c];
#pragma unroll
            for (int j = 0; j < 4; j++)
                bv[j] = Bs[q * BS_STRIDE + tx + 16 * j];
#pragma unroll
            for (int i = 0; i < 8; i++)
#pragma unroll
                for (int j = 0; j < 4; j++)
                    acc[i][j] += a[i] * bv[j];
        }
    }

    int cnt = g_cnt[b];
    float ca = (float)(32 - cnt) * 0.03125f;   // weight on T[t]
    float cc = (float)cnt * 0.03125f;          // weight on T[0] = (0,1,0,1,...)

#pragma unroll
    for (int i = 0; i < 8; i++) {
        int tl = tbase + i;
        int tg = t0 + tl;
        int4 m = Ms[tl];
        const float* Tt  = &g_T[tg  * DD + d0];
        const float* Tm0 = &g_T[m.x * DD + d0];
        const float* Tm1 = &g_T[m.y * DD + d0];
        const float* Tm2 = &g_T[m.z * DD + d0];
        const float* Tm3 = &g_T[m.w * DD + d0];
        float* orow = &out[((size_t)(b * TT + tg)) * DD + d0];
#pragma unroll
        for (int j = 0; j < 4; j++) {
            int dl = tx + 16 * j;
            int dg = d0 + dl;
            float v = acc[i][j]
                    + Tm0[dl] + Tm1[dl] + Tm2[dl] + Tm3[dl]
                    + ca * Tt[dl]
                    + ((dg & 1) ? cc : 0.f);
            orow[dl] = v;
        }
    }
}

// ---------------------------------------------------------------------------
extern "C" void kernel_launch(void* const* d_in, const int* in_sizes, int n_in,
                              void* d_out, int out_size) {
    const float* x  = (const float*)d_in[0];   // (16,512,32)
    const int*   xm = (const int*)  d_in[1];   // (16,512,4)
    const float* w  = (const float*)d_in[2];   // (512,32,3)
    float* out = (float*)d_out;                // (16,512,512)

    build_table_kernel<<<TT, 256>>>();
    dft_argmax_kernel<<<BB * NCH, 256>>>(x);
    dim3 grid(DD / BN, TT / BM, BB);
    fused_main_kernel<<<grid, 256>>>(x, xm, w, out);
}

// round 11
// speedup vs baseline: 2.9785x; 1.4788x over previous
#include <cuda_runtime.h>
#include <math.h>

#define BB 16
#define TT 512
#define NCH 32
#define DD 512
#define KQ 96          // 3*32 contraction length

#define BM 128
#define BN 64
#define RS 132         // Xs transposed row stride (floats), 16B-aligned windows
#define BS2 72         // Bs row stride (floats), 16B-aligned

__device__ float g_T[TT * DD];     // sinusoid table: row r, col d
__device__ int   g_flag[BB * NCH]; // per-(b,n): 1 if rfft argmax == Nyquist bin

// ---------------------------------------------------------------------------
// Kernel 1: per-(b,n) DFT argmax over 257 rfft bins + build one table row.
// Block bn: (a) builds sinusoid table row bn (512 blocks cover all rows),
// (b) computes argmax of |rfft(x[b,:,n])| with residue-class accumulation:
// one rotator at 4*theta shared by 4 residue sums, phases applied at the end.
// Tie-break keeps the smaller bin (matches lax.top_k). Writes g_flag[bn].
// ---------------------------------------------------------------------------
__global__ __launch_bounds__(256) void dft_argmax_kernel(const float* __restrict__ x) {
    __shared__ float seq[TT];
    __shared__ float smax[256];
    __shared__ int   sidx[256];

    int bn = blockIdx.x;          // 0..511
    int b = bn >> 5;
    int n = bn & 31;
    int tid = threadIdx.x;

    // --- build sinusoid table row `bn` (float2 per thread) ---
    {
        const float kconst = 0.01798894603f;       // log(10000)/512
        float div = expf(-(float)(2 * tid) * kconst);
        float ang = (float)bn * div;
        float s, c;
        sincosf(ang, &s, &c);
        ((float2*)g_T)[bn * (DD / 2) + tid] = make_float2(s, c);
    }

    // --- load the sequence (strided gmem) ---
    seq[tid]       = x[(b * TT + tid) * NCH + n];
    seq[tid + 256] = x[(b * TT + tid + 256) * NCH + n];
    __syncthreads();

    float best;
    int   bidx;

    if (tid == 0) {
        // bin 0: |sum x|^2 ; bin 256: |sum (-1)^t x|^2
        float s0 = 0.f, s1 = 0.f;
        for (int t = 0; t < TT; t += 2) {
            float a = seq[t], c = seq[t + 1];
            s0 += a + c;
            s1 += a - c;
        }
        best = s0 * s0;
        bidx = 0;
        float m256 = s1 * s1;
        if (m256 > best) { best = m256; bidx = 256; }
    } else {
        int kk = tid;             // bins 1..255
        float th = 6.283185307179586f * (float)kk * (1.0f / 512.0f);
        float c4, s4;
        sincosf(4.0f * th, &s4, &c4);
        float c = 1.f, s = 0.f;
        float re[4] = {0.f, 0.f, 0.f, 0.f};
        float im[4] = {0.f, 0.f, 0.f, 0.f};

        for (int t = 0; t < TT; t += 4) {
            float v0 = seq[t], v1 = seq[t + 1], v2 = seq[t + 2], v3 = seq[t + 3];
            re[0] = fmaf(v0, c, re[0]);  im[0] = fmaf(v0, s, im[0]);
            re[1] = fmaf(v1, c, re[1]);  im[1] = fmaf(v1, s, im[1]);
            re[2] = fmaf(v2, c, re[2]);  im[2] = fmaf(v2, s, im[2]);
            re[3] = fmaf(v3, c, re[3]);  im[3] = fmaf(v3, s, im[3]);
            float cn = fmaf(c, c4, -s * s4);
            s = fmaf(s, c4, c * s4);
            c = cn;
        }
        // combine residue classes with phases e^{i*j*th}
        float R = re[0], I = im[0];
#pragma unroll
        for (int j = 1; j < 4; j++) {
            float cj, sj;
            sincosf((float)j * th, &sj, &cj);
            R += re[j] * cj - im[j] * sj;
            I += im[j] * cj + re[j] * sj;
        }
        best = R * R + I * I;
        bidx = kk;
    }

    smax[tid] = best;
    sidx[tid] = bidx;
    __syncthreads();
    for (int sft = 128; sft > 0; sft >>= 1) {
        if (tid < sft) {
            bool take = (smax[tid + sft] > smax[tid]) ||
                        (smax[tid + sft] == smax[tid] && sidx[tid + sft] < sidx[tid]);
            if (take) { smax[tid] = smax[tid + sft]; sidx[tid] = sidx[tid + sft]; }
        }
        __syncthreads();
    }
    if (tid == 0) g_flag[bn] = (sidx[0] == 256) ? 1 : 0;
}

// ---------------------------------------------------------------------------
// Kernel 2: fused circular conv (GEMM, K=96) + temporal rows + cycle rows.
// Tile 128(t) x 64(d), 256 threads, 8x4 microtile with CONTIGUOUS d mapping
// (dl = tx*4+j) so B loads and output stores are float4. Xs is transposed
// [c][t] so the 12-row A window loads as 3x LDS.128 reused across all 3 taps.
// Temporal lookups hit only table rows 0..6 -> staged in smem (LOOPED copy —
// 448 elements > 256 threads, the R8 bug).
// ---------------------------------------------------------------------------
__global__ __launch_bounds__(256) void fused_main_kernel(
    const float* __restrict__ x,
    const int*   __restrict__ xm,
    const float* __restrict__ w,
    float*       __restrict__ out)
{
    __shared__ float Xs[NCH * RS];     // [c][r], r = 0..129 (rows t0-1 .. t0+128)
    __shared__ float Bs[KQ * BS2];     // [q][dd] = w[(d0+dd)*96 + q]
    __shared__ float Trow[7 * BN];     // table rows 0..6 at cols d0..d0+63
    __shared__ int   sCnt;

    int b  = blockIdx.z;
    int t0 = blockIdx.y * BM;
    int d0 = blockIdx.x * BN;
    int tid = threadIdx.x;

    // Xs load: coalesced gmem, transposed smem write
    for (int i = tid; i < (BM + 2) * NCH; i += 256) {
        int r = i >> 5;
        int c = i & 31;
        int tt = (t0 + r - 1) & (TT - 1);       // circular pad
        Xs[c * RS + r] = x[(b * TT + tt) * NCH + c];
    }
    // Bs load: coalesced gmem (q fastest), strided smem write
    for (int i = tid; i < KQ * BN; i += 256) {
        int dd = i / KQ;
        int q  = i - dd * KQ;
        Bs[q * BS2 + dd] = w[(d0 + dd) * KQ + q];
    }
    // temporal rows 0..6  (448 elements -> must loop)
    for (int i = tid; i < 7 * BN; i += 256) {
        int r = i / BN;
        int c = i - r * BN;
        Trow[r * BN + c] = g_T[r * DD + d0 + c];
    }
    // per-batch Nyquist count from flags
    if (tid < 32) {
        int f = g_flag[b * NCH + tid];
        int c = __reduce_add_sync(0xffffffffu, f);
        if (tid == 0) sCnt = c;
    }
    __syncthreads();

    int tx = tid & 15;       // d block: dl = tx*4 + j
    int ty = tid >> 4;       // t block: tl = ty*8 + i
    int tbase = ty * 8;

    float acc[8][4];
#pragma unroll
    for (int i = 0; i < 8; i++)
#pragma unroll
        for (int j = 0; j < 4; j++) acc[i][j] = 0.f;

#pragma unroll 2
    for (int c = 0; c < NCH; c++) {
        float4 a0 = *(const float4*)&Xs[c * RS + tbase];
        float4 a1 = *(const float4*)&Xs[c * RS + tbase + 4];
        float4 a2 = *(const float4*)&Xs[c * RS + tbase + 8];
        float av[12] = {a0.x, a0.y, a0.z, a0.w,
                        a1.x, a1.y, a1.z, a1.w,
                        a2.x, a2.y, a2.z, a2.w};
#pragma unroll
        for (int k = 0; k < 3; k++) {
            float4 bv = *(const float4*)&Bs[(c * 3 + k) * BS2 + tx * 4];
#pragma unroll
            for (int i = 0; i < 8; i++) {
                float a = av[i + k];
                acc[i][0] = fmaf(a, bv.x, acc[i][0]);
                acc[i][1] = fmaf(a, bv.y, acc[i][1]);
                acc[i][2] = fmaf(a, bv.z, acc[i][2]);
                acc[i][3] = fmaf(a, bv.w, acc[i][3]);
            }
        }
    }

    int cnt = sCnt;
    float ca = (float)(32 - cnt) * 0.03125f;   // weight on T[t]
    float cc = (float)cnt * 0.03125f;          // weight on T[0] = (0,1,0,1,...)

#pragma unroll
    for (int i = 0; i < 8; i++) {
        int tl = tbase + i;
        int tg = t0 + tl;
        int4 m = ((const int4*)xm)[b * TT + tg];
        float4 tm0 = *(const float4*)&Trow[m.x * BN + tx * 4];
        float4 tm1 = *(const float4*)&Trow[m.y * BN + tx * 4];
        float4 tm2 = *(const float4*)&Trow[m.z * BN + tx * 4];
        float4 tm3 = *(const float4*)&Trow[m.w * BN + tx * 4];
        float4 tt4 = *(const float4*)&g_T[tg * DD + d0 + tx * 4];
        float4 o;
        o.x = acc[i][0] + tm0.x + tm1.x + tm2.x + tm3.x + ca * tt4.x;
        o.y = acc[i][1] + tm0.y + tm1.y + tm2.y + tm3.y + ca * tt4.y + cc;
        o.z = acc[i][2] + tm0.z + tm1.z + tm2.z + tm3.z + ca * tt4.z;
        o.w = acc[i][3] + tm0.w + tm1.w + tm2.w + tm3.w + ca * tt4.w + cc;
        *(float4*)&out[((size_t)(b * TT + tg)) * DD + d0 + tx * 4] = o;
    }
}

// ---------------------------------------------------------------------------
extern "C" void kernel_launch(void* const* d_in, const int* in_sizes, int n_in,
                              void* d_out, int out_size) {
    const float* x  = (const float*)d_in[0];   // (16,512,32)
    const int*   xm = (const int*)  d_in[1];   // (16,512,4)
    const float* w  = (const float*)d_in[2];   // (512,32,3)
    float* out = (float*)d_out;                // (16,512,512)

    dft_argmax_kernel<<<BB * NCH, 256>>>(x);
    dim3 grid(DD / BN, TT / BM, BB);
    fused_main_kernel<<<grid, 256>>>(x, xm, w, out);
}